// round 5
// baseline (speedup 1.0000x reference)
#include <cuda_runtime.h>
#include <math.h>
#include <stdint.h>

#define LAYERS 6
#define BATCH  4
#define SEQ    512
#define DIM    1024
#define HEADS  16
#define DHEAD  64
#define FFN    4096
#define TOKENS (BATCH*SEQ)          // 2048
#define ID     (HEADS*DHEAD)        // 1024

// weight slab sizes (floats)
#define W_QKV_FLOATS ((size_t)LAYERS*DIM*3*ID)   // 18,874,368
#define W_OUT_FLOATS ((size_t)LAYERS*ID*DIM)     //  6,291,456
#define W_1_FLOATS   ((size_t)LAYERS*DIM*FFN)    // 25,165,824
#define W_2_FLOATS   ((size_t)LAYERS*FFN*DIM)    // 25,165,824

// ---------------- scratch (allocation-guard safe) ----------------
__device__ float g_h  [TOKENS*DIM];
__device__ float g_qkv[TOKENS*3*ID];
__device__ float g_o  [TOKENS*ID];
__device__ float g_a  [(size_t)TOKENS*FFN];
__device__ float g_wr [W_QKV_FLOATS + W_OUT_FLOATS + W_1_FLOATS + W_2_FLOATS]; // 302MB

// ---------------- small PTX helpers ----------------
__device__ __forceinline__ uint32_t smem_u32(const void* p) {
    uint32_t a;
    asm("{ .reg .u64 t; cvta.to.shared.u64 t, %1; cvt.u32.u64 %0, t; }" : "=r"(a) : "l"(p));
    return a;
}
__device__ __forceinline__ void cp16(uint32_t dst, const void* src) {
    asm volatile("cp.async.cg.shared.global [%0], [%1], 16;" :: "r"(dst), "l"(src));
}
__device__ __forceinline__ void cp_commit() {
    asm volatile("cp.async.commit_group;" ::: "memory");
}
template<int N> __device__ __forceinline__ void cp_wait() {
    asm volatile("cp.async.wait_group %0;" :: "n"(N) : "memory");
}
__device__ __forceinline__ uint32_t f2tf(float x) {
    uint32_t u; asm("cvt.rna.tf32.f32 %0, %1;" : "=r"(u) : "f"(x)); return u;
}
__device__ __forceinline__ float tf32r(float x) { return __uint_as_float(f2tf(x)); }
__device__ __forceinline__ void mma_tf32(float* d, const uint32_t* a, const uint32_t* b) {
    asm volatile(
        "mma.sync.aligned.m16n8k8.row.col.f32.tf32.tf32.f32 "
        "{%0,%1,%2,%3}, {%4,%5,%6,%7}, {%8,%9}, {%0,%1,%2,%3};"
        : "+f"(d[0]), "+f"(d[1]), "+f"(d[2]), "+f"(d[3])
        : "r"(a[0]), "r"(a[1]), "r"(a[2]), "r"(a[3]), "r"(b[0]), "r"(b[1]));
}

// ---------------- weight rounding: out[i] = tf32(in[i]) ----------------
__global__ __launch_bounds__(256) void round_kernel(
    const float* __restrict__ in, float* __restrict__ out, int n4)
{
    int i = blockIdx.x * 256 + threadIdx.x;
    int stride = gridDim.x * 256;
    for (; i < n4; i += stride) {
        float4 v = ((const float4*)in)[i];
        v.x = tf32r(v.x); v.y = tf32r(v.y); v.z = tf32r(v.z); v.w = tf32r(v.w);
        ((float4*)out)[i] = v;
    }
}

// ---------------- LayerNorm (output pre-rounded to tf32) ----------------
__global__ __launch_bounds__(256) void ln_kernel(
    const float* __restrict__ x, const float* __restrict__ scale,
    const float* __restrict__ bias, float* __restrict__ out)
{
    __shared__ float wsum[8], wsq[8];
    int row = blockIdx.x, t = threadIdx.x;
    const float4* xr = (const float4*)(x + (size_t)row * DIM);
    float4 v = xr[t];
    float s  = v.x + v.y + v.z + v.w;
    float ss = v.x*v.x + v.y*v.y + v.z*v.z + v.w*v.w;
    #pragma unroll
    for (int o = 16; o; o >>= 1) {
        s  += __shfl_xor_sync(0xffffffffu, s,  o);
        ss += __shfl_xor_sync(0xffffffffu, ss, o);
    }
    if ((t & 31) == 0) { wsum[t >> 5] = s; wsq[t >> 5] = ss; }
    __syncthreads();
    float S = 0.f, SS = 0.f;
    #pragma unroll
    for (int i = 0; i < 8; i++) { S += wsum[i]; SS += wsq[i]; }
    float mean = S * (1.0f / DIM);
    float var  = SS * (1.0f / DIM) - mean * mean;
    float rstd = rsqrtf(var + 1e-5f);
    float4 sc = ((const float4*)scale)[t];
    float4 bi = ((const float4*)bias)[t];
    float4 o4;
    o4.x = tf32r((v.x - mean) * rstd * sc.x + bi.x);
    o4.y = tf32r((v.y - mean) * rstd * sc.y + bi.y);
    o4.z = tf32r((v.z - mean) * rstd * sc.z + bi.z);
    o4.w = tf32r((v.w - mean) * rstd * sc.w + bi.w);
    ((float4*)(out + (size_t)row * DIM))[t] = o4;
}

// ---------------- tf32 mma.sync GEMM ----------------
// C[M,N] = A[M,K] @ B[K,N]; A,B already tf32-rounded in memory.
// EPI 0: C = acc ; EPI 1: C = acc + bias + resid (in-place safe) ;
// EPI 2: C = tf32(gelu(acc + bias))
#define STAGES 4
#define APAD 20

__device__ __forceinline__ float gelu_exact(float v) {
    return 0.5f * v * (1.0f + erff(v * 0.70710678118654752f));
}

template<int BN, int EPI>
__global__ __launch_bounds__(256)
void tc_gemm(const float* __restrict__ A, const float* __restrict__ B,
             const float* __restrict__ bias, const float* __restrict__ resid,
             float* __restrict__ C, int N, int K)
{
    constexpr int BPAD = BN + 8;
    constexpr int A_ST = 128 * APAD;
    constexpr int B_ST = 16 * BPAD;
    constexpr int ST   = A_ST + B_ST;
    constexpr int WN   = BN / 4;     // warp tile N (64 or 32)
    constexpr int NT   = WN / 8;     // n-frags per warp (8 or 4)
    constexpr int BIT  = BN / 64;    // B fill iterations (4 or 2)

    extern __shared__ float smf[];
    const uint32_t sb = smem_u32(smf);
    const int tid  = threadIdx.x;
    const int lane = tid & 31, wid = tid >> 5;
    const int wm = wid & 1, wn = wid >> 1;
    const int m0 = blockIdx.y * 128;
    const int n0 = blockIdx.x * BN;

    auto fill = [&](int s, int k0) {
        uint32_t ab = sb + (uint32_t)(s * ST) * 4;
        uint32_t bb = ab + A_ST * 4;
        #pragma unroll
        for (int it = 0; it < 2; it++) {              // A: 128x16
            int idx = it * 256 + tid;
            int r = idx >> 2, sg = idx & 3;
            cp16(ab + (uint32_t)(r * APAD + sg * 4) * 4,
                 A + (size_t)(m0 + r) * K + k0 + sg * 4);
        }
        #pragma unroll
        for (int it = 0; it < BIT; it++) {            // B: 16xBN
            int idx = it * 256 + tid;
            int kk = idx / (BN / 4), sg = idx % (BN / 4);
            cp16(bb + (uint32_t)(kk * BPAD + sg * 4) * 4,
                 B + (size_t)(k0 + kk) * N + n0 + sg * 4);
        }
    };

    float acc[4][NT][4];
    #pragma unroll
    for (int i = 0; i < 4; i++)
        #pragma unroll
        for (int j = 0; j < NT; j++)
            #pragma unroll
            for (int q = 0; q < 4; q++) acc[i][j][q] = 0.f;

    const int NK = K >> 4;

    #pragma unroll
    for (int p = 0; p < STAGES - 1; p++) { fill(p, p * 16); cp_commit(); }

    const int fr = lane >> 2, fc = lane & 3;

    for (int i = 0; i < NK; i++) {
        cp_wait<STAGES - 2>();
        __syncthreads();
        if (i + STAGES - 1 < NK) fill((i + STAGES - 1) & (STAGES - 1), (i + STAGES - 1) * 16);
        cp_commit();

        const float* As = smf + (i & (STAGES - 1)) * ST;
        const float* Bs = As + A_ST;

        #pragma unroll
        for (int ks = 0; ks < 2; ks++) {
            uint32_t af[4][4], bf[NT][2];
            #pragma unroll
            for (int mt = 0; mt < 4; mt++) {
                const float* ap = As + (wm * 64 + mt * 16 + fr) * APAD + ks * 8 + fc;
                af[mt][0] = __float_as_uint(ap[0]);
                af[mt][1] = __float_as_uint(ap[8 * APAD]);
                af[mt][2] = __float_as_uint(ap[4]);
                af[mt][3] = __float_as_uint(ap[8 * APAD + 4]);
            }
            #pragma unroll
            for (int nt = 0; nt < NT; nt++) {
                const float* bp = Bs + (ks * 8 + fc) * BPAD + wn * WN + nt * 8 + fr;
                bf[nt][0] = __float_as_uint(bp[0]);
                bf[nt][1] = __float_as_uint(bp[4 * BPAD]);
            }
            #pragma unroll
            for (int mt = 0; mt < 4; mt++)
                #pragma unroll
                for (int nt = 0; nt < NT; nt++)
                    mma_tf32(acc[mt][nt], af[mt], bf[nt]);
        }
        __syncthreads();
    }

    // ---- epilogue ----
    #pragma unroll
    for (int mt = 0; mt < 4; mt++) {
        int row = m0 + wm * 64 + mt * 16 + fr;
        #pragma unroll
        for (int nt = 0; nt < NT; nt++) {
            int col = n0 + wn * WN + nt * 8 + fc * 2;
            float* d = acc[mt][nt];
            size_t i0 = (size_t)row * N + col;
            size_t i1 = (size_t)(row + 8) * N + col;
            float o0 = d[0], o1 = d[1], o2 = d[2], o3 = d[3];
            if (EPI == 1) {
                float bx = bias[col], by = bias[col + 1];
                o0 += bx + resid[i0]; o1 += by + resid[i0 + 1];
                o2 += bx + resid[i1]; o3 += by + resid[i1 + 1];
            }
            if (EPI == 2) {
                float bx = bias[col], by = bias[col + 1];
                o0 = tf32r(gelu_exact(o0 + bx)); o1 = tf32r(gelu_exact(o1 + by));
                o2 = tf32r(gelu_exact(o2 + bx)); o3 = tf32r(gelu_exact(o3 + by));
            }
            *(float2*)(C + i0) = make_float2(o0, o1);
            *(float2*)(C + i1) = make_float2(o2, o3);
        }
    }
}

// ---------------- Attention (output rounded to tf32) ----------------
#define ATTN_SMEM ((16*64 + 16*512 + 128*65) * 4)

__global__ __launch_bounds__(256) void attn_kernel(
    const float* __restrict__ qkv, float* __restrict__ o)
{
    extern __shared__ float sm[];
    float* qs  = sm;
    float* sc  = qs + 16 * 64;
    float* kvs = sc + 16 * 512;

    int t  = threadIdx.x;
    int bh = blockIdx.y;
    int b  = bh >> 4, h = bh & 15;
    int q0 = blockIdx.x * 16;

    const float* qbase = qkv + (size_t)(b * SEQ) * (3 * ID) + h * DHEAD;
    const float* kbase = qbase + ID;
    const float* vbase = qbase + 2 * ID;

    {
        int row = t >> 4, d4 = (t & 15) * 4;
        float4 v = *(const float4*)(qbase + (size_t)(q0 + row) * (3 * ID) + d4);
        *(float4*)&qs[row * 64 + d4] = v;
    }

    for (int kc = 0; kc < 4; kc++) {
        __syncthreads();
        #pragma unroll
        for (int i = 0; i < 8; i++) {
            int f = i * 256 + t;
            int row = f >> 4, d4 = (f & 15) * 4;
            float4 v = *(const float4*)(kbase + (size_t)(kc * 128 + row) * (3 * ID) + d4);
            kvs[row * 65 + d4 + 0] = v.x;
            kvs[row * 65 + d4 + 1] = v.y;
            kvs[row * 65 + d4 + 2] = v.z;
            kvs[row * 65 + d4 + 3] = v.w;
        }
        __syncthreads();
        #pragma unroll
        for (int i = 0; i < 8; i++) {
            int idx = i * 256 + t;
            int qi = idx >> 7, kj = idx & 127;
            const float* qrow = &qs[qi * 64];
            const float* krow = &kvs[kj * 65];
            float s = 0.f;
            #pragma unroll 16
            for (int d = 0; d < 64; d++) s += qrow[d] * krow[d];
            sc[qi * 512 + kc * 128 + kj] = s * 0.125f;
        }
    }
    __syncthreads();

    int wid = t >> 5, lane = t & 31;
    for (int qi = wid; qi < 16; qi += 8) {
        float* srow = &sc[qi * 512];
        float m = -1e30f;
        float e[16];
        #pragma unroll
        for (int i = 0; i < 16; i++) m = fmaxf(m, srow[i * 32 + lane]);
        #pragma unroll
        for (int off = 16; off; off >>= 1) m = fmaxf(m, __shfl_xor_sync(0xffffffffu, m, off));
        float sum = 0.f;
        #pragma unroll
        for (int i = 0; i < 16; i++) { e[i] = __expf(srow[i * 32 + lane] - m); sum += e[i]; }
        #pragma unroll
        for (int off = 16; off; off >>= 1) sum += __shfl_xor_sync(0xffffffffu, sum, off);
        float inv = 1.0f / sum;
        #pragma unroll
        for (int i = 0; i < 16; i++) srow[i * 32 + lane] = e[i] * inv;
    }
    __syncthreads();

    float oacc[4] = {0.f, 0.f, 0.f, 0.f};
    for (int vc = 0; vc < 4; vc++) {
        #pragma unroll
        for (int i = 0; i < 8; i++) {
            int f = i * 256 + t;
            int row = f >> 4, d4 = (f & 15) * 4;
            float4 v = *(const float4*)(vbase + (size_t)(vc * 128 + row) * (3 * ID) + d4);
            kvs[row * 65 + d4 + 0] = v.x;
            kvs[row * 65 + d4 + 1] = v.y;
            kvs[row * 65 + d4 + 2] = v.z;
            kvs[row * 65 + d4 + 3] = v.w;
        }
        __syncthreads();
        #pragma unroll
        for (int i = 0; i < 4; i++) {
            int idx = i * 256 + t;
            int qi = idx >> 6, d = idx & 63;
            const float* prow = &sc[qi * 512 + vc * 128];
            float a = oacc[i];
            #pragma unroll 16
            for (int j = 0; j < 128; j++) a += prow[j] * kvs[j * 65 + d];
            oacc[i] = a;
        }
        __syncthreads();
    }
    #pragma unroll
    for (int i = 0; i < 4; i++) {
        int idx = i * 256 + t;
        int qi = idx >> 6, d = idx & 63;
        o[(size_t)(b * SEQ + q0 + qi) * ID + h * DHEAD + d] = tf32r(oacc[i]);
    }
}

// ---------------- driver ----------------
extern "C" void kernel_launch(void* const* d_in, const int* in_sizes, int n_in,
                              void* d_out, int out_size)
{
    const float* x_in = (const float*)d_in[0];
    const float* ln1s = (const float*)d_in[1];
    const float* ln1b = (const float*)d_in[2];
    const float* wqkv = (const float*)d_in[3];
    const float* wout = (const float*)d_in[4];
    const float* bout = (const float*)d_in[5];
    const float* ln2s = (const float*)d_in[6];
    const float* ln2b = (const float*)d_in[7];
    const float* w1   = (const float*)d_in[8];
    const float* b1   = (const float*)d_in[9];
    const float* w2   = (const float*)d_in[10];
    const float* b2   = (const float*)d_in[11];
    float* x = (float*)d_out;

    void* p;
    cudaGetSymbolAddress(&p, g_h);   float* gh   = (float*)p;
    cudaGetSymbolAddress(&p, g_qkv); float* gqkv = (float*)p;
    cudaGetSymbolAddress(&p, g_o);   float* go   = (float*)p;
    cudaGetSymbolAddress(&p, g_a);   float* ga   = (float*)p;
    cudaGetSymbolAddress(&p, g_wr);  float* gwr  = (float*)p;

    float* rw_qkv = gwr;
    float* rw_out = rw_qkv + W_QKV_FLOATS;
    float* rw_1   = rw_out + W_OUT_FLOATS;
    float* rw_2   = rw_1   + W_1_FLOATS;

    cudaFuncSetAttribute(attn_kernel, cudaFuncAttributeMaxDynamicSharedMemorySize, ATTN_SMEM);
    const int SM256 = STAGES * (128*APAD + 16*(256+8)) * 4;   // 108544
    const int SM128 = STAGES * (128*APAD + 16*(128+8)) * 4;   //  75776
    cudaFuncSetAttribute(tc_gemm<256,0>, cudaFuncAttributeMaxDynamicSharedMemorySize, SM256);
    cudaFuncSetAttribute(tc_gemm<256,2>, cudaFuncAttributeMaxDynamicSharedMemorySize, SM256);
    cudaFuncSetAttribute(tc_gemm<128,1>, cudaFuncAttributeMaxDynamicSharedMemorySize, SM128);

    // pre-round all weights to tf32 (idempotent, graph-capturable)
    round_kernel<<<2048, 256>>>(wqkv, rw_qkv, (int)(W_QKV_FLOATS / 4));
    round_kernel<<<2048, 256>>>(wout, rw_out, (int)(W_OUT_FLOATS / 4));
    round_kernel<<<2048, 256>>>(w1,   rw_1,   (int)(W_1_FLOATS   / 4));
    round_kernel<<<2048, 256>>>(w2,   rw_2,   (int)(W_2_FLOATS   / 4));

    cudaMemcpyAsync(x, x_in, (size_t)TOKENS * DIM * sizeof(float),
                    cudaMemcpyDeviceToDevice);

    for (int l = 0; l < LAYERS; l++) {
        const float* l1s = ln1s + l * DIM;
        const float* l1b = ln1b + l * DIM;
        const float* wq  = rw_qkv + (size_t)l * DIM * (3 * ID);
        const float* wo  = rw_out + (size_t)l * ID * DIM;
        const float* bo  = bout + l * DIM;
        const float* l2s = ln2s + l * DIM;
        const float* l2b = ln2b + l * DIM;
        const float* w1l = rw_1 + (size_t)l * DIM * FFN;
        const float* b1l = b1 + l * FFN;
        const float* w2l = rw_2 + (size_t)l * FFN * DIM;
        const float* b2l = b2 + l * DIM;

        // h = LN1(x)  (tf32-rounded)
        ln_kernel<<<TOKENS, 256>>>(x, l1s, l1b, gh);
        // qkv = h @ wqkv
        tc_gemm<256,0><<<dim3(3 * ID / 256, TOKENS / 128), 256, SM256>>>(
            gh, wq, nullptr, nullptr, gqkv, 3 * ID, DIM);
        // attention (output tf32-rounded)
        attn_kernel<<<dim3(SEQ / 16, BATCH * HEADS), 256, ATTN_SMEM>>>(gqkv, go);
        // x = x + o @ wo + bo
        tc_gemm<128,1><<<dim3(DIM / 128, TOKENS / 128), 256, SM128>>>(
            go, wo, bo, x, x, DIM, ID);
        // h = LN2(x)  (tf32-rounded)
        ln_kernel<<<TOKENS, 256>>>(x, l2s, l2b, gh);
        // a = tf32(gelu(h @ w1 + b1))
        tc_gemm<256,2><<<dim3(FFN / 256, TOKENS / 128), 256, SM256>>>(
            gh, w1l, b1l, nullptr, ga, FFN, DIM);
        // x = x + a @ w2 + b2
        tc_gemm<128,1><<<dim3(DIM / 128, TOKENS / 128), 256, SM128>>>(
            ga, w2l, b2l, x, x, DIM, FFN);
    }
}

// round 7
// speedup vs baseline: 1.5752x; 1.5752x over previous
#include <cuda_runtime.h>
#include <math.h>
#include <stdint.h>

#define LAYERS 6
#define BATCH  4
#define SEQ    512
#define DIM    1024
#define HEADS  16
#define DHEAD  64
#define FFN    4096
#define TOKENS (BATCH*SEQ)          // 2048
#define ID     (HEADS*DHEAD)        // 1024

// ---------------- scratch (allocation-guard safe) ----------------
__device__ float g_h  [TOKENS*DIM];
__device__ float g_qkv[TOKENS*3*ID];
__device__ float g_o  [TOKENS*ID];
__device__ float g_a  [(size_t)TOKENS*FFN];

// ---------------- small PTX helpers ----------------
__device__ __forceinline__ uint32_t smem_u32(const void* p) {
    uint32_t a;
    asm("{ .reg .u64 t; cvta.to.shared.u64 t, %1; cvt.u32.u64 %0, t; }" : "=r"(a) : "l"(p));
    return a;
}
__device__ __forceinline__ void cp16(uint32_t dst, const void* src) {
    asm volatile("cp.async.cg.shared.global [%0], [%1], 16;" :: "r"(dst), "l"(src));
}
__device__ __forceinline__ void cp_commit() {
    asm volatile("cp.async.commit_group;" ::: "memory");
}
template<int N> __device__ __forceinline__ void cp_wait() {
    asm volatile("cp.async.wait_group %0;" :: "n"(N) : "memory");
}
__device__ __forceinline__ uint32_t f2tf(float x) {
    uint32_t u; asm("cvt.rna.tf32.f32 %0, %1;" : "=r"(u) : "f"(x)); return u;
}
__device__ __forceinline__ float tf32r(float x) { return __uint_as_float(f2tf(x)); }
__device__ __forceinline__ void mma_tf32(float* d, const uint32_t* a, const uint32_t* b) {
    asm volatile(
        "mma.sync.aligned.m16n8k8.row.col.f32.tf32.tf32.f32 "
        "{%0,%1,%2,%3}, {%4,%5,%6,%7}, {%8,%9}, {%0,%1,%2,%3};"
        : "+f"(d[0]), "+f"(d[1]), "+f"(d[2]), "+f"(d[3])
        : "r"(a[0]), "r"(a[1]), "r"(a[2]), "r"(a[3]), "r"(b[0]), "r"(b[1]));
}

// ---------------- LayerNorm ----------------
__global__ __launch_bounds__(256) void ln_kernel(
    const float* __restrict__ x, const float* __restrict__ scale,
    const float* __restrict__ bias, float* __restrict__ out)
{
    __shared__ float wsum[8], wsq[8];
    int row = blockIdx.x, t = threadIdx.x;
    const float4* xr = (const float4*)(x + (size_t)row * DIM);
    float4 v = xr[t];
    float s  = v.x + v.y + v.z + v.w;
    float ss = v.x*v.x + v.y*v.y + v.z*v.z + v.w*v.w;
    #pragma unroll
    for (int o = 16; o; o >>= 1) {
        s  += __shfl_xor_sync(0xffffffffu, s,  o);
        ss += __shfl_xor_sync(0xffffffffu, ss, o);
    }
    if ((t & 31) == 0) { wsum[t >> 5] = s; wsq[t >> 5] = ss; }
    __syncthreads();
    float S = 0.f, SS = 0.f;
    #pragma unroll
    for (int i = 0; i < 8; i++) { S += wsum[i]; SS += wsq[i]; }
    float mean = S * (1.0f / DIM);
    float var  = SS * (1.0f / DIM) - mean * mean;
    float rstd = rsqrtf(var + 1e-5f);
    float4 sc = ((const float4*)scale)[t];
    float4 bi = ((const float4*)bias)[t];
    float4 o4;
    o4.x = (v.x - mean) * rstd * sc.x + bi.x;
    o4.y = (v.y - mean) * rstd * sc.y + bi.y;
    o4.z = (v.z - mean) * rstd * sc.z + bi.z;
    o4.w = (v.w - mean) * rstd * sc.w + bi.w;
    ((float4*)(out + (size_t)row * DIM))[t] = o4;
}

// ---------------- tf32 mma.sync GEMM (in-loop cvt, 256 threads) ----------------
#define STAGES 4
#define APAD 20

__device__ __forceinline__ float gelu_exact(float v) {
    return 0.5f * v * (1.0f + erff(v * 0.70710678118654752f));
}

template<int BN, int EPI>
__global__ __launch_bounds__(256)
void tc_gemm(const float* __restrict__ A, const float* __restrict__ B,
             const float* __restrict__ bias, const float* __restrict__ resid,
             float* __restrict__ C, int N, int K)
{
    constexpr int BPAD = BN + 8;
    constexpr int A_ST = 128 * APAD;
    constexpr int B_ST = 16 * BPAD;
    constexpr int ST   = A_ST + B_ST;
    constexpr int WN   = BN / 4;     // warp tile N (64 or 32)
    constexpr int NT   = WN / 8;     // n-frags per warp (8 or 4)
    constexpr int BIT  = BN / 64;    // B fill iterations (4 or 2)

    extern __shared__ float smf[];
    const uint32_t sb = smem_u32(smf);
    const int tid  = threadIdx.x;
    const int lane = tid & 31, wid = tid >> 5;
    const int wm = wid & 1, wn = wid >> 1;
    const int m0 = blockIdx.y * 128;
    const int n0 = blockIdx.x * BN;

    auto fill = [&](int s, int k0) {
        uint32_t ab = sb + (uint32_t)(s * ST) * 4;
        uint32_t bb = ab + A_ST * 4;
        #pragma unroll
        for (int it = 0; it < 2; it++) {              // A: 128x16
            int idx = it * 256 + tid;
            int r = idx >> 2, sg = idx & 3;
            cp16(ab + (uint32_t)(r * APAD + sg * 4) * 4,
                 A + (size_t)(m0 + r) * K + k0 + sg * 4);
        }
        #pragma unroll
        for (int it = 0; it < BIT; it++) {            // B: 16xBN
            int idx = it * 256 + tid;
            int kk = idx / (BN / 4), sg = idx % (BN / 4);
            cp16(bb + (uint32_t)(kk * BPAD + sg * 4) * 4,
                 B + (size_t)(k0 + kk) * N + n0 + sg * 4);
        }
    };

    float acc[4][NT][4];
    #pragma unroll
    for (int i = 0; i < 4; i++)
        #pragma unroll
        for (int j = 0; j < NT; j++)
            #pragma unroll
            for (int q = 0; q < 4; q++) acc[i][j][q] = 0.f;

    const int NK = K >> 4;

    #pragma unroll
    for (int p = 0; p < STAGES - 1; p++) { fill(p, p * 16); cp_commit(); }

    const int fr = lane >> 2, fc = lane & 3;

    for (int i = 0; i < NK; i++) {
        cp_wait<STAGES - 2>();
        __syncthreads();
        if (i + STAGES - 1 < NK) fill((i + STAGES - 1) & (STAGES - 1), (i + STAGES - 1) * 16);
        cp_commit();

        const float* As = smf + (i & (STAGES - 1)) * ST;
        const float* Bs = As + A_ST;

        #pragma unroll
        for (int ks = 0; ks < 2; ks++) {
            uint32_t af[4][4], bf[NT][2];
            #pragma unroll
            for (int mt = 0; mt < 4; mt++) {
                const float* ap = As + (wm * 64 + mt * 16 + fr) * APAD + ks * 8 + fc;
                af[mt][0] = f2tf(ap[0]);
                af[mt][1] = f2tf(ap[8 * APAD]);
                af[mt][2] = f2tf(ap[4]);
                af[mt][3] = f2tf(ap[8 * APAD + 4]);
            }
            #pragma unroll
            for (int nt = 0; nt < NT; nt++) {
                const float* bp = Bs + (ks * 8 + fc) * BPAD + wn * WN + nt * 8 + fr;
                bf[nt][0] = f2tf(bp[0]);
                bf[nt][1] = f2tf(bp[4 * BPAD]);
            }
            #pragma unroll
            for (int mt = 0; mt < 4; mt++)
                #pragma unroll
                for (int nt = 0; nt < NT; nt++)
                    mma_tf32(acc[mt][nt], af[mt], bf[nt]);
        }
        __syncthreads();
    }

    // ---- epilogue ----
    #pragma unroll
    for (int mt = 0; mt < 4; mt++) {
        int row = m0 + wm * 64 + mt * 16 + fr;
        #pragma unroll
        for (int nt = 0; nt < NT; nt++) {
            int col = n0 + wn * WN + nt * 8 + fc * 2;
            float* d = acc[mt][nt];
            size_t i0 = (size_t)row * N + col;
            size_t i1 = (size_t)(row + 8) * N + col;
            float o0 = d[0], o1 = d[1], o2 = d[2], o3 = d[3];
            if (EPI == 1) {
                float bx = bias[col], by = bias[col + 1];
                o0 += bx + resid[i0]; o1 += by + resid[i0 + 1];
                o2 += bx + resid[i1]; o3 += by + resid[i1 + 1];
            }
            if (EPI == 2) {
                float bx = bias[col], by = bias[col + 1];
                o0 = gelu_exact(o0 + bx); o1 = gelu_exact(o1 + by);
                o2 = gelu_exact(o2 + bx); o3 = gelu_exact(o3 + by);
            }
            *(float2*)(C + i0) = make_float2(o0, o1);
            *(float2*)(C + i1) = make_float2(o2, o3);
        }
    }
}

// ---------------- Flash attention with tf32 mma.sync ----------------
// grid (SEQ/64, BATCH*HEADS), 128 threads (4 warps, 16 q-rows each).
// K chunks of 64 keys, online softmax, double-buffered K/V via cp.async.
// B operand of mma.row.col is [n][k]-indexed: K's natural [j][d] serves QK^T,
// V's natural [j][d] is [k][n] for P@V. No transposes anywhere.
#define FA_PAD 72
#define FA_TILE (64*FA_PAD)
#define FA_SMEM (6*FA_TILE*4)      // Q,P + 2K + 2V  = 110592 B

__global__ __launch_bounds__(128) void fattn_kernel(
    const float* __restrict__ qkv, float* __restrict__ o)
{
    extern __shared__ float sm[];
    float* Qs = sm;                       // [64][72]
    float* Ps = Qs + FA_TILE;             // [64][72]
    float* Ks = Ps + FA_TILE;             // [2][64][72]
    float* Vs = Ks + 2*FA_TILE;           // [2][64][72]
    const uint32_t sb = smem_u32(sm);
    const uint32_t Qb = sb;
    const uint32_t Kb = sb + (uint32_t)(2*FA_TILE)*4;
    const uint32_t Vb = sb + (uint32_t)(4*FA_TILE)*4;

    const int tid = threadIdx.x, lane = tid & 31, w = tid >> 5;
    const int fr = lane >> 2, fc = lane & 3;
    const int bh = blockIdx.y;
    const int b = bh >> 4, h = bh & 15;
    const int q0 = blockIdx.x * 64;

    const float* qbase = qkv + (size_t)(b * SEQ) * (3 * ID) + h * DHEAD;
    const float* kbase = qbase + ID;
    const float* vbase = qbase + 2 * ID;

    // Q fill: 64 rows x 64 floats
    #pragma unroll
    for (int it = 0; it < 8; it++) {
        int idx = it * 128 + tid;
        int r = idx >> 4, s4 = idx & 15;
        cp16(Qb + (uint32_t)(r * FA_PAD + s4 * 4) * 4,
             qbase + (size_t)(q0 + r) * 3072 + s4 * 4);
    }
    auto fillKV = [&](int c, int buf) {
        #pragma unroll
        for (int it = 0; it < 8; it++) {
            int idx = it * 128 + tid;
            int r = idx >> 4, s4 = idx & 15;
            cp16(Kb + (uint32_t)((buf * 64 + r) * FA_PAD + s4 * 4) * 4,
                 kbase + (size_t)(c * 64 + r) * 3072 + s4 * 4);
            cp16(Vb + (uint32_t)((buf * 64 + r) * FA_PAD + s4 * 4) * 4,
                 vbase + (size_t)(c * 64 + r) * 3072 + s4 * 4);
        }
    };
    fillKV(0, 0); cp_commit();

    float accO[8][4];
    #pragma unroll
    for (int nt = 0; nt < 8; nt++)
        #pragma unroll
        for (int q = 0; q < 4; q++) accO[nt][q] = 0.f;
    float M0 = -1e30f, M1 = -1e30f, L0 = 0.f, L1 = 0.f;

    const float* Prow0 = Ps + (w * 16 + fr) * FA_PAD;
    const int prow0_off = (w * 16 + fr) * FA_PAD;

    for (int c = 0; c < SEQ / 64; c++) {
        cp_wait<0>();
        __syncthreads();                       // data ready + all warps past last chunk
        if (c + 1 < SEQ / 64) { fillKV(c + 1, (c + 1) & 1); cp_commit(); }

        const float* Kc = Ks + (c & 1) * FA_TILE;
        const float* Vc = Vs + (c & 1) * FA_TILE;

        // ---- S = Q @ K^T (warp rows w*16..w*16+15, cols 0..63) ----
        float sacc[8][4];
        #pragma unroll
        for (int nt = 0; nt < 8; nt++)
            #pragma unroll
            for (int q = 0; q < 4; q++) sacc[nt][q] = 0.f;
        #pragma unroll
        for (int ks = 0; ks < 8; ks++) {
            uint32_t af[4];
            const float* qp = Qs + (w * 16 + fr) * FA_PAD + ks * 8 + fc;
            af[0] = f2tf(qp[0]);
            af[1] = f2tf(qp[8 * FA_PAD]);
            af[2] = f2tf(qp[4]);
            af[3] = f2tf(qp[8 * FA_PAD + 4]);
            #pragma unroll
            for (int nt = 0; nt < 8; nt++) {
                const float* kp = Kc + (nt * 8 + fr) * FA_PAD + ks * 8 + fc;
                uint32_t bf[2] = { f2tf(kp[0]), f2tf(kp[4]) };
                mma_tf32(sacc[nt], af, bf);
            }
        }

        // ---- online softmax (rows fr / fr+8; row data across 4 fc-lanes) ----
        float mx0 = -1e30f, mx1 = -1e30f;
        #pragma unroll
        for (int nt = 0; nt < 8; nt++) {
            sacc[nt][0] *= 0.125f; sacc[nt][1] *= 0.125f;
            sacc[nt][2] *= 0.125f; sacc[nt][3] *= 0.125f;
            mx0 = fmaxf(mx0, fmaxf(sacc[nt][0], sacc[nt][1]));
            mx1 = fmaxf(mx1, fmaxf(sacc[nt][2], sacc[nt][3]));
        }
        mx0 = fmaxf(mx0, __shfl_xor_sync(0xffffffffu, mx0, 1));
        mx0 = fmaxf(mx0, __shfl_xor_sync(0xffffffffu, mx0, 2));
        mx1 = fmaxf(mx1, __shfl_xor_sync(0xffffffffu, mx1, 1));
        mx1 = fmaxf(mx1, __shfl_xor_sync(0xffffffffu, mx1, 2));
        float Mn0 = fmaxf(M0, mx0), Mn1 = fmaxf(M1, mx1);
        float a0 = __expf(M0 - Mn0), a1 = __expf(M1 - Mn1);
        float s0 = 0.f, s1 = 0.f;
        #pragma unroll
        for (int nt = 0; nt < 8; nt++) {
            float p0 = __expf(sacc[nt][0] - Mn0), p1 = __expf(sacc[nt][1] - Mn0);
            float p2 = __expf(sacc[nt][2] - Mn1), p3 = __expf(sacc[nt][3] - Mn1);
            s0 += p0 + p1; s1 += p2 + p3;
            *(float2*)(Ps + prow0_off + nt * 8 + 2 * fc) =
                make_float2(tf32r(p0), tf32r(p1));
            *(float2*)(Ps + prow0_off + 8 * FA_PAD + nt * 8 + 2 * fc) =
                make_float2(tf32r(p2), tf32r(p3));
            accO[nt][0] *= a0; accO[nt][1] *= a0;
            accO[nt][2] *= a1; accO[nt][3] *= a1;
        }
        s0 += __shfl_xor_sync(0xffffffffu, s0, 1);
        s0 += __shfl_xor_sync(0xffffffffu, s0, 2);
        s1 += __shfl_xor_sync(0xffffffffu, s1, 1);
        s1 += __shfl_xor_sync(0xffffffffu, s1, 2);
        L0 = L0 * a0 + s0; L1 = L1 * a1 + s1;
        M0 = Mn0; M1 = Mn1;
        __syncwarp();                      // Ps visible within warp

        // ---- O += P @ V ----
        #pragma unroll
        for (int ks = 0; ks < 8; ks++) {
            uint32_t af[4];
            const float* pp = Prow0 + ks * 8 + fc;
            af[0] = __float_as_uint(pp[0]);
            af[1] = __float_as_uint(pp[8 * FA_PAD]);
            af[2] = __float_as_uint(pp[4]);
            af[3] = __float_as_uint(pp[8 * FA_PAD + 4]);
            #pragma unroll
            for (int nt = 0; nt < 8; nt++) {
                const float* vp = Vc + (ks * 8 + fc) * FA_PAD + nt * 8 + fr;
                uint32_t bf[2] = { f2tf(vp[0]), f2tf(vp[4 * FA_PAD]) };
                mma_tf32(accO[nt], af, bf);
            }
        }
    }

    float inv0 = 1.0f / L0, inv1 = 1.0f / L1;
    size_t t0 = (size_t)(b * SEQ + q0 + w * 16 + fr);
    #pragma unroll
    for (int nt = 0; nt < 8; nt++) {
        int col = h * DHEAD + nt * 8 + 2 * fc;
        *(float2*)(o + t0 * ID + col) =
            make_float2(accO[nt][0] * inv0, accO[nt][1] * inv0);
        *(float2*)(o + (t0 + 8) * ID + col) =
            make_float2(accO[nt][2] * inv1, accO[nt][3] * inv1);
    }
}

// ---------------- driver ----------------
extern "C" void kernel_launch(void* const* d_in, const int* in_sizes, int n_in,
                              void* d_out, int out_size)
{
    const float* x_in = (const float*)d_in[0];
    const float* ln1s = (const float*)d_in[1];
    const float* ln1b = (const float*)d_in[2];
    const float* wqkv = (const float*)d_in[3];
    const float* wout = (const float*)d_in[4];
    const float* bout = (const float*)d_in[5];
    const float* ln2s = (const float*)d_in[6];
    const float* ln2b = (const float*)d_in[7];
    const float* w1   = (const float*)d_in[8];
    const float* b1   = (const float*)d_in[9];
    const float* w2   = (const float*)d_in[10];
    const float* b2   = (const float*)d_in[11];
    float* x = (float*)d_out;

    void* p;
    cudaGetSymbolAddress(&p, g_h);   float* gh   = (float*)p;
    cudaGetSymbolAddress(&p, g_qkv); float* gqkv = (float*)p;
    cudaGetSymbolAddress(&p, g_o);   float* go   = (float*)p;
    cudaGetSymbolAddress(&p, g_a);   float* ga   = (float*)p;

    const int SM256 = STAGES * (128*APAD + 16*(256+8)) * 4;   // 108544
    const int SM128 = STAGES * (128*APAD + 16*(128+8)) * 4;   //  75776
    cudaFuncSetAttribute(tc_gemm<256,0>, cudaFuncAttributeMaxDynamicSharedMemorySize, SM256);
    cudaFuncSetAttribute(tc_gemm<256,2>, cudaFuncAttributeMaxDynamicSharedMemorySize, SM256);
    cudaFuncSetAttribute(tc_gemm<128,1>, cudaFuncAttributeMaxDynamicSharedMemorySize, SM128);
    cudaFuncSetAttribute(fattn_kernel, cudaFuncAttributeMaxDynamicSharedMemorySize, FA_SMEM);

    cudaMemcpyAsync(x, x_in, (size_t)TOKENS * DIM * sizeof(float),
                    cudaMemcpyDeviceToDevice);

    for (int l = 0; l < LAYERS; l++) {
        const float* l1s = ln1s + l * DIM;
        const float* l1b = ln1b + l * DIM;
        const float* wq  = wqkv + (size_t)l * DIM * (3 * ID);
        const float* wo  = wout + (size_t)l * ID * DIM;
        const float* bo  = bout + l * DIM;
        const float* l2s = ln2s + l * DIM;
        const float* l2b = ln2b + l * DIM;
        const float* w1l = w1 + (size_t)l * DIM * FFN;
        const float* b1l = b1 + l * FFN;
        const float* w2l = w2 + (size_t)l * FFN * DIM;
        const float* b2l = b2 + l * DIM;

        // h = LN1(x)
        ln_kernel<<<TOKENS, 256>>>(x, l1s, l1b, gh);
        // qkv = h @ wqkv
        tc_gemm<256,0><<<dim3(3 * ID / 256, TOKENS / 128), 256, SM256>>>(
            gh, wq, nullptr, nullptr, gqkv, 3 * ID, DIM);
        // attention (tf32 flash)
        fattn_kernel<<<dim3(SEQ / 64, BATCH * HEADS), 128, FA_SMEM>>>(gqkv, go);
        // x = x + o @ wo + bo
        tc_gemm<128,1><<<dim3(DIM / 128, TOKENS / 128), 256, SM128>>>(
            go, wo, bo, x, x, DIM, ID);
        // h = LN2(x)
        ln_kernel<<<TOKENS, 256>>>(x, l2s, l2b, gh);
        // a = gelu(h @ w1 + b1)
        tc_gemm<256,2><<<dim3(FFN / 256, TOKENS / 128), 256, SM256>>>(
            gh, w1l, b1l, nullptr, ga, FFN, DIM);
        // x = x + a @ w2 + b2
        tc_gemm<128,1><<<dim3(DIM / 128, TOKENS / 128), 256, SM128>>>(
            ga, w2l, b2l, x, x, DIM, FFN);
    }
}